// round 8
// baseline (speedup 1.0000x reference)
#include <cuda_runtime.h>
#include <cuda_fp16.h>

// Shapes (fixed by the reference setup)
#define BATCH 64
#define T     4096
#define DIN   128
#define DST   256
#define DOUT  128
#define BT    (BATCH * T)   // 262144 (b,t) rows

// ---------------------------------------------------------------------------
// Device-global scratch (no cudaMalloc allowed).
//   g_uB : precomputed input projection uB[b][t][s]   (fp32, 256 MB)
//   g_X  : full state history x[b][t][s]              (fp32, 256 MB)
//   g_Bt : B transposed [k][s] for conflict-free GEMM staging
//   g_Ct : C transposed [s][o]
// ---------------------------------------------------------------------------
__device__ float g_uB[(size_t)BT * DST];
__device__ float g_X [(size_t)BT * DST];
__device__ float g_Bt[DIN * DST];
__device__ float g_Ct[DST * DOUT];

// ---------------------------------------------------------------------------
// Kernel 0: transpose B [s][k] -> Bt [k][s] and C [o][s] -> Ct [s][o]
// (both are 32768 elements; trivial one-shot)
// ---------------------------------------------------------------------------
__global__ void transpose_BC(const float* __restrict__ B,
                             const float* __restrict__ C) {
    int tid = blockIdx.x * blockDim.x + threadIdx.x;
    if (tid < DST * DIN) {
        int s = tid / DIN, k = tid % DIN;
        g_Bt[k * DST + s] = B[tid];
        int o = tid / DST, s2 = tid % DST;
        g_Ct[s2 * DOUT + o] = C[tid];
    }
}

// ---------------------------------------------------------------------------
// Kernel 1: uB[b][t][s] = sum_i u[b][t][i] * B[s][i]
// GEMM: M = BT rows (64 per block), N = 256 (all), K = 128 (un-tiled).
// Transposed shared tiles -> all inner-loop LDS are vectorized, conflict-free.
// Per block: 64*256*128 = 2.1 MMAC -> ~32768 cyc (FFMA floor, 8x8 reg tile).
// ---------------------------------------------------------------------------
#define P1_BP 260              // Bt row pad (floats): 1040 B, 16B-aligned rows
#define P1_UP 68               // u  row pad (floats): 272 B,  16B-aligned rows
#define P1_SMEM ((DIN * P1_BP + DIN * P1_UP) * 4)   // 167,936 B

__global__ void __launch_bounds__(256, 1) uB_gemm(const float* __restrict__ u) {
    extern __shared__ float sh[];
    float* Bts = sh;                       // [128][260]  Bt[k][s]
    float* uts = sh + DIN * P1_BP;         // [128][68]   ut[k][r]
    const int tid = threadIdx.x;
    const long row0 = (long)blockIdx.x * 64;

    // Stage Bt (coalesced global read, conflict-free STS: consecutive tid = consecutive s)
    for (int i = tid; i < DIN * DST; i += 256) {
        int k = i >> 8, s = i & 255;
        Bts[k * P1_BP + s] = g_Bt[i];
    }
    // Stage u transposed (coalesced read: consecutive tid = consecutive k)
    for (int i = tid; i < 64 * DIN; i += 256) {
        int r = i >> 7, k = i & 127;
        uts[k * P1_UP + r] = u[(row0 + r) * DIN + k];
    }
    __syncthreads();

    const int tx = tid & 31, ty = tid >> 5;    // 32 col-groups x 8 row-groups
    const int c0 = tx * 8, r0 = ty * 8;

    float acc[8][8];
#pragma unroll
    for (int i = 0; i < 8; i++)
#pragma unroll
        for (int j = 0; j < 8; j++) acc[i][j] = 0.f;

#pragma unroll 4
    for (int k = 0; k < DIN; k++) {
        float4 b0 = *(const float4*)&Bts[k * P1_BP + c0];
        float4 b1 = *(const float4*)&Bts[k * P1_BP + c0 + 4];
        float4 u0 = *(const float4*)&uts[k * P1_UP + r0];
        float4 u1 = *(const float4*)&uts[k * P1_UP + r0 + 4];
        float bv[8] = {b0.x, b0.y, b0.z, b0.w, b1.x, b1.y, b1.z, b1.w};
        float uv[8] = {u0.x, u0.y, u0.z, u0.w, u1.x, u1.y, u1.z, u1.w};
#pragma unroll
        for (int i = 0; i < 8; i++)
#pragma unroll
            for (int j = 0; j < 8; j++)
                acc[i][j] = fmaf(uv[i], bv[j], acc[i][j]);
    }

#pragma unroll
    for (int i = 0; i < 8; i++) {
        float* dst = &g_uB[(row0 + r0 + i) * (long)DST + c0];
        *(float4*)(dst)     = make_float4(acc[i][0], acc[i][1], acc[i][2], acc[i][3]);
        *(float4*)(dst + 4) = make_float4(acc[i][4], acc[i][5], acc[i][6], acc[i][7]);
    }
}

// ---------------------------------------------------------------------------
// Kernel 2: the serial recurrence. One block per batch chain (64 blocks).
// Thread s owns output state s; A row s lives in 128 half2 REGISTERS
// (shared-BW floor would otherwise bind at >=1024 cyc/step; register A + HFMA2
// puts the step at the 512-cyc FMA-pipe floor).
// x is double-buffered in shared as half2; one __syncthreads per step.
// 8 independent fp16 accumulation chains (4 half2 accs) keep the fp16
// accumulation error ~2e-5 abs/step; fp32 combine + fp32 uB + fp32 tanh.
// ---------------------------------------------------------------------------
__global__ void __launch_bounds__(256, 1) ssm_recur(const float* __restrict__ A) {
    const int s = threadIdx.x;
    const int b = blockIdx.x;

    // Load A row s -> 128 half2 registers (one-time; amortized over 4096 steps)
    __half2 a2[128];
    {
        const float2* Arow = (const float2*)(A + (size_t)s * DST);
#pragma unroll
        for (int j = 0; j < 128; j++) {
            float2 v = Arow[j];
            a2[j] = __floats2half2_rn(v.x, v.y);
        }
    }

    __shared__ __half2 xsh[2][128];
    if (s < 128) xsh[0][s] = __float2half2_rn(0.f);   // x_0 = 0
    __syncthreads();

    const float* uBb = g_uB + (size_t)b * T * DST;
    float*       Xb  = g_X  + (size_t)b * T * DST;

    int cur = 0;
    float ub = uBb[s];                      // uB for step 0
    for (int t = 0; t < T; t++) {
        // Prefetch next step's uB one full step (~700 cyc) ahead of use
        float ub_next = (t + 1 < T) ? uBb[(size_t)(t + 1) * DST + s] : 0.f;

        __half2 acc0 = __float2half2_rn(0.f);
        __half2 acc1 = acc0, acc2 = acc0, acc3 = acc0;
        const uint4* xp = (const uint4*)xsh[cur];
#pragma unroll
        for (int j = 0; j < 32; j++) {
            uint4 xv = xp[j];                         // 4 half2 per LDS.128 (broadcast)
            acc0 = __hfma2(a2[4 * j + 0], *(__half2*)&xv.x, acc0);
            acc1 = __hfma2(a2[4 * j + 1], *(__half2*)&xv.y, acc1);
            acc2 = __hfma2(a2[4 * j + 2], *(__half2*)&xv.z, acc2);
            acc3 = __hfma2(a2[4 * j + 3], *(__half2*)&xv.w, acc3);
        }
        float2 f0 = __half22float2(acc0);
        float2 f1 = __half22float2(acc1);
        float2 f2 = __half22float2(acc2);
        float2 f3 = __half22float2(acc3);
        float sum = ((f0.x + f0.y) + (f1.x + f1.y)) + ((f2.x + f2.y) + (f3.x + f3.y));

        float xn = tanhf(sum + ub);
        Xb[(size_t)t * DST + s] = xn;                 // fp32 state history (coalesced)

        ((__half*)xsh[cur ^ 1])[s] = __float2half_rn(xn);
        __syncthreads();                              // writes visible before next read
        cur ^= 1;
        ub = ub_next;
    }
}

// ---------------------------------------------------------------------------
// Kernel 3: y[row][o] = sum_s X[row][s] * C[o][s]  (M = BT, N = 128, K = 256)
// Same transposed-tile structure as kernel 1; 4x8 register tile.
// ---------------------------------------------------------------------------
#define P3_CP 132
#define P3_XP 68
#define P3_SMEM ((DST * P3_CP + DST * P3_XP) * 4)   // 204,800 B

__global__ void __launch_bounds__(256, 1) y_gemm(float* __restrict__ out) {
    extern __shared__ float sh[];
    float* Cts = sh;                       // [256][132]  Ct[s][o]
    float* Xts = sh + DST * P3_CP;         // [256][68]   Xt[s][r]
    const int tid = threadIdx.x;
    const long row0 = (long)blockIdx.x * 64;

    for (int i = tid; i < DST * DOUT; i += 256) {
        int s = i >> 7, o = i & 127;
        Cts[s * P3_CP + o] = g_Ct[i];      // coalesced read, conflict-free STS
    }
    for (int i = tid; i < 64 * DST; i += 256) {
        int r = i >> 8, si = i & 255;
        Xts[si * P3_XP + r] = g_X[(row0 + r) * DST + si];  // coalesced read
    }
    __syncthreads();

    const int tx = tid & 15, ty = tid >> 4;    // 16 col-groups x 16 row-groups
    const int c0 = tx * 8, r0 = ty * 4;

    float acc[4][8];
#pragma unroll
    for (int i = 0; i < 4; i++)
#pragma unroll
        for (int j = 0; j < 8; j++) acc[i][j] = 0.f;

#pragma unroll 4
    for (int k = 0; k < DST; k++) {
        float4 cA = *(const float4*)&Cts[k * P3_CP + c0];
        float4 cB = *(const float4*)&Cts[k * P3_CP + c0 + 4];
        float4 xv = *(const float4*)&Xts[k * P3_XP + r0];
        float cv[8] = {cA.x, cA.y, cA.z, cA.w, cB.x, cB.y, cB.z, cB.w};
        float rv[4] = {xv.x, xv.y, xv.z, xv.w};
#pragma unroll
        for (int i = 0; i < 4; i++)
#pragma unroll
            for (int j = 0; j < 8; j++)
                acc[i][j] = fmaf(rv[i], cv[j], acc[i][j]);
    }

#pragma unroll
    for (int i = 0; i < 4; i++) {
        float* dst = out + (row0 + r0 + i) * (long)DOUT + c0;
        *(float4*)(dst)     = make_float4(acc[i][0], acc[i][1], acc[i][2], acc[i][3]);
        *(float4*)(dst + 4) = make_float4(acc[i][4], acc[i][5], acc[i][6], acc[i][7]);
    }
}

// ---------------------------------------------------------------------------
// Launch: 4 kernels on the default stream (graph-capturable; no syncs/allocs).
// ---------------------------------------------------------------------------
extern "C" void kernel_launch(void* const* d_in, const int* in_sizes, int n_in,
                              void* d_out, int out_size) {
    const float* u = (const float*)d_in[0];   // [64,4096,128]
    const float* A = (const float*)d_in[1];   // [256,256]
    const float* B = (const float*)d_in[2];   // [256,128]
    const float* C = (const float*)d_in[3];   // [128,256]
    float* out = (float*)d_out;               // [64,4096,128] fp32

    // Idempotent attribute sets (host-side, capture-safe)
    cudaFuncSetAttribute(uB_gemm, cudaFuncAttributeMaxDynamicSharedMemorySize, P1_SMEM);
    cudaFuncSetAttribute(y_gemm,  cudaFuncAttributeMaxDynamicSharedMemorySize, P3_SMEM);

    transpose_BC<<<128, 256>>>(B, C);
    uB_gemm<<<BT / 64, 256, P1_SMEM>>>(u);
    ssm_recur<<<BATCH, 256>>>(A);
    y_gemm<<<BT / 64, 256, P3_SMEM>>>(out);
}

// round 9
// speedup vs baseline: 1.5135x; 1.5135x over previous
#include <cuda_runtime.h>
#include <cuda_fp16.h>
#include <cstdint>

#define BATCH 64
#define T     4096
#define DIN   128
#define DST   256
#define DOUT  128

// ---------------------------------------------------------------------------
// PTX helpers (sm_90+ cluster / mbarrier / st.async)
// ---------------------------------------------------------------------------
__device__ __forceinline__ uint32_t ctarank() {
    uint32_t r; asm("mov.u32 %0, %%cluster_ctarank;" : "=r"(r)); return r;
}
__device__ __forceinline__ uint32_t smem_u32(const void* p) {
    uint32_t a;
    asm("{ .reg .u64 t; cvta.to.shared.u64 t, %1; cvt.u32.u64 %0, t; }"
        : "=r"(a) : "l"(p));
    return a;
}
__device__ __forceinline__ uint32_t mapa_u32(uint32_t l, uint32_t r) {
    uint32_t v; asm("mapa.shared::cluster.u32 %0, %1, %2;" : "=r"(v) : "r"(l), "r"(r));
    return v;
}
__device__ __forceinline__ void mbar_init(uint32_t m, uint32_t cnt) {
    asm volatile("mbarrier.init.shared.b64 [%0], %1;" :: "r"(m), "r"(cnt) : "memory");
}
__device__ __forceinline__ void mbar_expect(uint32_t m, uint32_t tx) {
    asm volatile("mbarrier.arrive.expect_tx.shared.b64 _, [%0], %1;"
                 :: "r"(m), "r"(tx) : "memory");
}
__device__ __forceinline__ void mbar_wait(uint32_t m, uint32_t parity) {
    asm volatile(
        "{\n\t.reg .pred P;\n\t"
        "W_%=:\n\t"
        "mbarrier.try_wait.parity.acquire.cluster.shared::cta.b64 P, [%0], %1, 0x989680;\n\t"
        "@!P bra W_%=;\n\t}"
        :: "r"(m), "r"(parity) : "memory");
}
__device__ __forceinline__ void st_async_b32(uint32_t raddr, uint32_t val, uint32_t rmbar) {
    asm volatile("st.async.shared::cluster.mbarrier::complete_tx::bytes.b32 [%0], %1, [%2];"
                 :: "r"(raddr), "r"(val), "r"(rmbar) : "memory");
}
#define CLUSTER_SYNC() do { \
    asm volatile("barrier.cluster.arrive.aligned;" ::: "memory"); \
    asm volatile("barrier.cluster.wait.aligned;"   ::: "memory"); \
} while (0)

// A-matvec partial: 64 HFMA2 over this thread's K-half of x (4 fp16 chains of 16)
#define DO_A(xbase) do {                                                 \
    const uint4* xp_ = (const uint4*)((xbase) + (h << 7));               \
    _Pragma("unroll")                                                    \
    for (int j_ = 0; j_ < 16; j_++) {                                    \
        uint4 v_ = xp_[j_];                                              \
        qa0 = __hfma2(a2[4*j_+0], *(__half2*)&v_.x, qa0);                \
        qa1 = __hfma2(a2[4*j_+1], *(__half2*)&v_.y, qa1);                \
        qa2 = __hfma2(a2[4*j_+2], *(__half2*)&v_.z, qa2);                \
        qa3 = __hfma2(a2[4*j_+3], *(__half2*)&v_.w, qa3);                \
    } } while (0)

// C-matvec partial: 32 HFMA2 over this thread's 64-state K-group (4 chains of 8)
#define DO_Y(xbase) do {                                                 \
    const uint4* yp_ = (const uint4*)((xbase) + (g << 6));               \
    _Pragma("unroll")                                                    \
    for (int j_ = 0; j_ < 8; j_++) {                                     \
        uint4 v_ = yp_[j_];                                              \
        qc0 = __hfma2(c2[4*j_+0], *(__half2*)&v_.x, qc0);                \
        qc1 = __hfma2(c2[4*j_+1], *(__half2*)&v_.y, qc1);                \
        qc2 = __hfma2(c2[4*j_+2], *(__half2*)&v_.z, qc2);                \
        qc3 = __hfma2(c2[4*j_+3], *(__half2*)&v_.w, qc3);                \
    } } while (0)

__device__ __forceinline__ float hsum8(__half2 q0, __half2 q1, __half2 q2, __half2 q3) {
    float2 r0 = __half22float2(q0), r1 = __half22float2(q1);
    float2 r2 = __half22float2(q2), r3 = __half22float2(q3);
    return ((r0.x + r0.y) + (r1.x + r1.y)) + ((r2.x + r2.y) + (r3.x + r3.y));
}

// ---------------------------------------------------------------------------
// Fused SSM: 64 clusters of 2 CTAs (one cluster per batch), 256 thr/CTA.
// CTA rank r owns states [r*128, r*128+128) and outputs [r*64, r*64+64).
// Thread (sl, h): A/B partial for state sg = r*128+sl over K-half h.
// Thread (o,  g): y partial for output r*64+o over state-group g (64 states).
// Note g>>1 == h, so a thread's y-group lives on the same CTA as its A-half:
// everything with h==rank runs BEFORE the mbarrier wait (fills exchange latency).
// ---------------------------------------------------------------------------
__global__ void __launch_bounds__(256, 1) __cluster_dims__(2, 1, 1)
ssm_fused(const float* __restrict__ u, const float* __restrict__ A,
          const float* __restrict__ B, const float* __restrict__ C,
          float* __restrict__ out)
{
    __shared__ __align__(16) __half xs[2][DST];     // x_t (t&1 selects buffer)
    __shared__ __align__(16) __half us[2][DIN];     // u_t fp16
    __shared__ float psum[128];                     // h=1 -> h=0 A+B partial
    __shared__ float yps[3][64];                    // y partials (g=0,1,2)
    __shared__ __align__(8) unsigned long long mb[2];

    const int tid = threadIdx.x;
    const int h   = tid >> 7;            // K-half for A/B
    const int sl  = tid & 127;           // local state
    const int g   = tid >> 6;            // K-group for y
    const int o   = tid & 63;            // y output
    const uint32_t rank = ctarank();
    const uint32_t peer = rank ^ 1u;
    const int b   = blockIdx.x >> 1;
    const int own = (h == (int)rank);
    const int sg  = ((int)rank << 7) + sl;

    const uint32_t mb0 = smem_u32(&mb[0]), mb1 = smem_u32(&mb[1]);
    const uint32_t xs0 = smem_u32(&xs[0][0]), xs1 = smem_u32(&xs[1][0]);

    if (tid == 0) {
        mbar_init(mb0, 1); mbar_init(mb1, 1);
        mbar_expect(mb0, 256); mbar_expect(mb1, 256);   // arm first phases
    }
    if (tid < 128) ((uint32_t*)&xs[0][0])[tid] = 0u;     // x_0 = 0 (512B)

    // One-time register tiles (fp32 -> fp16), amortized over 4096 steps
    __half2 a2[64], b2[32], c2[32];
    {
        const float2* Ar = (const float2*)(A + (size_t)sg * DST + (h << 7));
#pragma unroll
        for (int j = 0; j < 64; j++) { float2 v = Ar[j]; a2[j] = __floats2half2_rn(v.x, v.y); }
        const float2* Br = (const float2*)(B + (size_t)sg * DIN + (h << 6));
#pragma unroll
        for (int j = 0; j < 32; j++) { float2 v = Br[j]; b2[j] = __floats2half2_rn(v.x, v.y); }
        const float2* Cr = (const float2*)(C + (size_t)(((int)rank << 6) + o) * DST + (g << 6));
#pragma unroll
        for (int j = 0; j < 32; j++) { float2 v = Cr[j]; c2[j] = __floats2half2_rn(v.x, v.y); }
    }

    const size_t urow = (size_t)b * T;
    if (tid < DIN) us[0][tid] = __float2half(u[urow * DIN + tid]);
    float un = (tid < DIN) ? u[(urow + 1) * DIN + tid] : 0.f;   // u_1 prefetch

    __syncthreads();     // local init visible
    CLUSTER_SYNC();      // peer mbarriers armed before any st.async

    const uint32_t rx0 = mapa_u32(xs0, peer), rx1 = mapa_u32(xs1, peer);
    const uint32_t rm0 = mapa_u32(mb0, peer), rm1 = mapa_u32(mb1, peer);

    int ph0 = 0, ph1 = 0;
    float* outb = out + urow * DOUT + ((int)rank << 6) + o;
    const __half2 z = __float2half2_rn(0.f);

#pragma unroll 1
    for (int t = 0; t < T; ++t) {
        const int cur = t & 1, nxt = cur ^ 1;
        const __half* xcur = xs[cur];

        // prefetch u_{t+2}
        float un2 = 0.f;
        if (tid < DIN && (t + 2) < T) un2 = u[(urow + t + 2) * DIN + tid];

        // --- u.B partial: no dependency on x ---
        __half2 qb0 = z, qb1 = z, qb2 = z, qb3 = z;
        {
            const uint4* up = (const uint4*)(&us[cur][h << 6]);
#pragma unroll
            for (int j = 0; j < 8; j++) {
                uint4 v = up[j];
                qb0 = __hfma2(b2[4*j+0], *(__half2*)&v.x, qb0);
                qb1 = __hfma2(b2[4*j+1], *(__half2*)&v.y, qb1);
                qb2 = __hfma2(b2[4*j+2], *(__half2*)&v.z, qb2);
                qb3 = __hfma2(b2[4*j+3], *(__half2*)&v.w, qb3);
            }
        }
        __half2 qa0 = z, qa1 = z, qa2 = z, qa3 = z;
        __half2 qc0 = z, qc1 = z, qc2 = z, qc3 = z;

        if (own) { DO_A(xcur); DO_Y(xcur); }        // local-half work fills transit
        if (t > 0) {                                // wait for peer half of x_t
            if (cur == 0) { mbar_wait(mb0, ph0); ph0 ^= 1; if (tid == 0) mbar_expect(mb0, 256); }
            else          { mbar_wait(mb1, ph1); ph1 ^= 1; if (tid == 0) mbar_expect(mb1, 256); }
        }
        if (!own) { DO_A(xcur); DO_Y(xcur); }

        const float pAB = hsum8(qa0, qa1, qa2, qa3) + hsum8(qb0, qb1, qb2, qb3);
        const float fy  = hsum8(qc0, qc1, qc2, qc3);

        if (h) psum[sl] = pAB;
        if (g < 3) yps[g][o] = fy;
        if (tid < DIN) us[nxt][tid] = __float2half(un);
        un = un2;
        __syncthreads();                            // bar1: partials visible

        if (h == 0) {                               // combine, tanh, publish x_{t+1}
            const float xv = tanhf(pAB + psum[sl]);
            const unsigned hv  = (unsigned)__half_as_ushort(__float2half_rn(xv));
            const unsigned nb  = __shfl_down_sync(0xffffffffu, hv, 1);
            if ((tid & 1) == 0) {
                const unsigned pk = hv | (nb << 16);
                *((uint32_t*)&xs[nxt][sg]) = pk;                     // local half
                const uint32_t ra = (nxt ? rx1 : rx0) + (uint32_t)(sg << 1);
                st_async_b32(ra, pk, nxt ? rm1 : rm0);               // peer half + tx
            }
        }
        if (g == 3 && t > 0)                        // y_{t-1} = x_t @ C^T
            outb[(size_t)(t - 1) * DOUT] = fy + yps[0][o] + yps[1][o] + yps[2][o];
        __syncthreads();                            // bar2: protect psum/yps/x reuse
    }

    // Epilogue: y_{T-1} = x_T @ C^T  (x_T lives in xs[T&1] after final exchange)
    {
        const int cur = T & 1;                      // = 0
        if (cur == 0) mbar_wait(mb0, ph0); else mbar_wait(mb1, ph1);
        __half2 qc0 = z, qc1 = z, qc2 = z, qc3 = z;
        const __half* xcur = xs[cur];
        DO_Y(xcur);
        const float fy = hsum8(qc0, qc1, qc2, qc3);
        if (g < 3) yps[g][o] = fy;
        __syncthreads();
        if (g == 3)
            outb[(size_t)(T - 1) * DOUT] = fy + yps[0][o] + yps[1][o] + yps[2][o];
    }
    CLUSTER_SYNC();                                 // no early exit under peer traffic
}

// ---------------------------------------------------------------------------
// Single launch: 128 CTAs = 64 two-CTA clusters, one wave on 148 SMs.
// ---------------------------------------------------------------------------
extern "C" void kernel_launch(void* const* d_in, const int* in_sizes, int n_in,
                              void* d_out, int out_size) {
    const float* u = (const float*)d_in[0];   // [64,4096,128]
    const float* A = (const float*)d_in[1];   // [256,256]
    const float* B = (const float*)d_in[2];   // [256,128]
    const float* C = (const float*)d_in[3];   // [128,256]
    float* out = (float*)d_out;               // [64,4096,128]

    ssm_fused<<<BATCH * 2, 256>>>(u, A, B, C, out);
}